// round 1
// baseline (speedup 1.0000x reference)
#include <cuda_runtime.h>
#include <cstdint>

// CenterLoss collapses: mask is one-hot(labels), so only B entries of the
// [B, C] distance matrix survive; the clip() turns the other B*(C-1) zeros
// into a closed-form constant B*(C-1)*1e-12. No GEMM needed.

#define CL_BATCH 1024
#define CL_FEAT  128
#define CL_NUMC  100000

// Scratch for per-sample clipped distances (no cudaMalloc allowed).
__device__ float g_cl_partial[CL_BATCH];

__global__ void __launch_bounds__(256)
center_loss_per_sample(const float* __restrict__ x,
                       const int* __restrict__ labels,
                       const float* __restrict__ centers)
{
    const int warp = (blockIdx.x * blockDim.x + threadIdx.x) >> 5;
    const int lane = threadIdx.x & 31;
    if (warp >= CL_BATCH) return;

    const int lbl = labels[warp];

    // 128 floats per row = 32 lanes x float4
    const float4 xv = reinterpret_cast<const float4*>(x + (size_t)warp * CL_FEAT)[lane];
    const float4 cv = reinterpret_cast<const float4*>(centers + (size_t)lbl * CL_FEAT)[lane];

    // Per-lane partial of  ||x||^2 + ||c||^2 - 2 x.c  (linear in per-lane sums)
    float p = 0.f;
    p += xv.x * xv.x + cv.x * cv.x - 2.f * xv.x * cv.x;
    p += xv.y * xv.y + cv.y * cv.y - 2.f * xv.y * cv.y;
    p += xv.z * xv.z + cv.z * cv.z - 2.f * xv.z * cv.z;
    p += xv.w * xv.w + cv.w * cv.w - 2.f * xv.w * cv.w;

    // Warp tree-reduce (deterministic)
    #pragma unroll
    for (int off = 16; off > 0; off >>= 1)
        p += __shfl_xor_sync(0xFFFFFFFFu, p, off);

    if (lane == 0) {
        // clip(d, 1e-12, 1e12) per reference
        p = fminf(fmaxf(p, 1e-12f), 1e12f);
        g_cl_partial[warp] = p;
    }
}

__global__ void __launch_bounds__(256)
center_loss_reduce(float* __restrict__ out)
{
    __shared__ float sm[256];
    const int tid = threadIdx.x;

    // Each thread sums 4 partials in a fixed order -> deterministic.
    float s = 0.f;
    #pragma unroll
    for (int k = 0; k < CL_BATCH / 256; ++k)
        s += g_cl_partial[tid * (CL_BATCH / 256) + k];
    sm[tid] = s;
    __syncthreads();

    #pragma unroll
    for (int stride = 128; stride > 0; stride >>= 1) {
        if (tid < stride) sm[tid] += sm[tid + stride];
        __syncthreads();
    }

    if (tid == 0) {
        // Masked-out zeros each clip to 1e-12: B*(C-1) of them.
        double total = (double)sm[0]
                     + (double)CL_BATCH * (double)(CL_NUMC - 1) * 1e-12;
        out[0] = (float)(total / (double)CL_BATCH);
    }
}

extern "C" void kernel_launch(void* const* d_in, const int* in_sizes, int n_in,
                              void* d_out, int out_size)
{
    // metadata order: x [B,F] f32, labels [B] i32, centers [C,F] f32
    const float* x       = (const float*)d_in[0];
    const int*   labels  = (const int*)d_in[1];
    const float* centers = (const float*)d_in[2];
    float*       out     = (float*)d_out;

    // 1024 warps -> 128 blocks of 256 threads (8 warps each)
    center_loss_per_sample<<<(CL_BATCH * 32) / 256, 256>>>(x, labels, centers);
    center_loss_reduce<<<1, 256>>>(out);
}

// round 2
// speedup vs baseline: 1.1507x; 1.1507x over previous
#include <cuda_runtime.h>
#include <cstdint>

// CenterLoss collapses: mask is one-hot(labels), so only the B diagonal-like
// entries of the [B, C] distance matrix survive; the clip() turns the other
// B*(C-1) zeros into the closed-form constant B*(C-1)*1e-12. No GEMM.
//
// Single fused kernel: per-sample distance + block partial + fence-reduction
// (last block finalizes in a FIXED order -> deterministic).

#define CL_BATCH 1024
#define CL_FEAT  128
#define CL_NUMC  100000

#define CL_BLOCKS 128          // 256 thr = 8 warps = 8 samples per block
#define CL_THREADS 256

__device__ float g_cl_partial[CL_BLOCKS];
__device__ unsigned int g_cl_done = 0;   // reset to 0 by last block each call

__global__ void __launch_bounds__(CL_THREADS)
center_loss_fused(const float* __restrict__ x,
                  const int* __restrict__ labels,
                  const float* __restrict__ centers,
                  float* __restrict__ out)
{
    const int tid     = threadIdx.x;
    const int lane    = tid & 31;
    const int warpInB = tid >> 5;                       // 0..7
    const int sample  = blockIdx.x * 8 + warpInB;       // 0..1023

    // ---- per-sample squared distance (one warp per sample) ----
    const int lbl = labels[sample];

    const float4 xv = reinterpret_cast<const float4*>(x + (size_t)sample * CL_FEAT)[lane];
    const float4 cv = reinterpret_cast<const float4*>(centers + (size_t)lbl * CL_FEAT)[lane];

    float4 d;
    d.x = xv.x - cv.x; d.y = xv.y - cv.y; d.z = xv.z - cv.z; d.w = xv.w - cv.w;
    // Note: (x-c)^2 expanded == x^2 + c^2 - 2xc in real arithmetic; float
    // rounding differs slightly from the reference's expanded form, but far
    // below the 1e-3 threshold (and it's numerically *better*). Keep expanded
    // form anyway to match reference rounding as closely as possible:
    float p = 0.f;
    p += xv.x * xv.x + cv.x * cv.x - 2.f * xv.x * cv.x;
    p += xv.y * xv.y + cv.y * cv.y - 2.f * xv.y * cv.y;
    p += xv.z * xv.z + cv.z * cv.z - 2.f * xv.z * cv.z;
    p += xv.w * xv.w + cv.w * cv.w - 2.f * xv.w * cv.w;
    (void)d;

    #pragma unroll
    for (int off = 16; off > 0; off >>= 1)
        p += __shfl_xor_sync(0xFFFFFFFFu, p, off);

    // ---- block partial: 8 clipped per-sample values, fixed-order sum ----
    __shared__ float sm[8];
    if (lane == 0)
        sm[warpInB] = fminf(fmaxf(p, 1e-12f), 1e12f);
    __syncthreads();

    __shared__ bool amLast;
    if (tid == 0) {
        float bp = 0.f;
        #pragma unroll
        for (int i = 0; i < 8; ++i) bp += sm[i];      // fixed order
        g_cl_partial[blockIdx.x] = bp;
        __threadfence();                              // make partial visible
        unsigned int n = atomicAdd(&g_cl_done, 1u);
        amLast = (n == CL_BLOCKS - 1);
    }
    __syncthreads();

    // ---- last block finalizes in a fixed order (deterministic) ----
    if (amLast && warpInB == 0) {
        // 128 partials: each lane sums 4 in fixed order, then shuffle tree.
        float s = 0.f;
        #pragma unroll
        for (int k = 0; k < CL_BLOCKS / 32; ++k)
            s += __ldcg(&g_cl_partial[lane * (CL_BLOCKS / 32) + k]);
        #pragma unroll
        for (int off = 16; off > 0; off >>= 1)
            s += __shfl_xor_sync(0xFFFFFFFFu, s, off);

        if (lane == 0) {
            double total = (double)s
                         + (double)CL_BATCH * (double)(CL_NUMC - 1) * 1e-12;
            out[0] = (float)(total / (double)CL_BATCH);
            g_cl_done = 0;            // reset for next (graph replay) call
        }
    }
}

extern "C" void kernel_launch(void* const* d_in, const int* in_sizes, int n_in,
                              void* d_out, int out_size)
{
    const float* x       = (const float*)d_in[0];
    const int*   labels  = (const int*)d_in[1];
    const float* centers = (const float*)d_in[2];
    float*       out     = (float*)d_out;

    center_loss_fused<<<CL_BLOCKS, CL_THREADS>>>(x, labels, centers, out);
}